// round 14
// baseline (speedup 1.0000x reference)
#include <cuda_runtime.h>

#define B_N   8
#define H_IN  384
#define W_IN  384
#define HO    382
#define WO    382
#define KST   64
#define NB    9
#define HOWO  (HO * WO)

// Weights/biases in constant memory. k-major native layout: cW[k*64 + s].
// One LDC.128 fetches W[k][4q..4q+3] = four states of the same k, halving
// const-port traffic (LDC->LDC structural floor is 8 cyc) vs pairwise LDC.64.
__constant__ float cW[NB * KST];   // 2304 B
__constant__ float cB[KST];        // 256 B

// ---- packed f32x2 helpers (Blackwell) ----
__device__ __forceinline__ unsigned long long dup2(float v) {
    unsigned long long r;
    asm("mov.b64 %0, {%1, %1};" : "=l"(r) : "f"(v));
    return r;
}
__device__ __forceinline__ unsigned long long fma2(unsigned long long a,
                                                   unsigned long long b,
                                                   unsigned long long c) {
    unsigned long long d;
    asm("fma.rn.f32x2 %0, %1, %2, %3;" : "=l"(d) : "l"(a), "l"(b), "l"(c));
    return d;
}
__device__ __forceinline__ unsigned long long mul2(unsigned long long a,
                                                   unsigned long long b) {
    unsigned long long d;
    asm("mul.rn.f32x2 %0, %1, %2;" : "=l"(d) : "l"(a), "l"(b));
    return d;
}
__device__ __forceinline__ unsigned long long add2(unsigned long long a,
                                                   unsigned long long b) {
    unsigned long long d;
    asm("add.rn.f32x2 %0, %1, %2;" : "=l"(d) : "l"(a), "l"(b));
    return d;
}
__device__ __forceinline__ void unpack2(unsigned long long d, float& lo, float& hi) {
    asm("mov.b64 {%0, %1}, %2;" : "=f"(lo), "=f"(hi) : "l"(d));
}

__device__ __forceinline__ ulonglong2 cquad(const float* p) {
    return *reinterpret_cast<const ulonglong2*>(p);   // LDC.128 (16B-aligned)
}

// Block: (32, 2) = 64 threads, no smem, no barriers, no row guard
// (382 = 2 * 191). Thread = 4 consecutive output columns of one output row.
// Grid: (3, 191, 8) = 4584 blocks. Quad-state inner loop: 16 iterations of
// 4 Fock states each; 10 LDC.128 per iteration (vs 20 LDC.64 pairwise).
__global__ __launch_bounds__(64, 16) void qconv_kernel(
    const float* __restrict__ x, const int* __restrict__ keys,
    float* __restrict__ out)
{
    const float c0 = 1.5707963267948966f; // pi/2

    const int bz = blockIdx.z;
    const int i  = blockIdx.y * 2 + threadIdx.y;          // 0..381 exact
    const int j0 = blockIdx.x * 128 + threadIdx.x * 4;    // mult of 4, <= 380

    const float* xb = x + bz * (H_IN * W_IN);

    // 3x6 patch block: float4 + predicated float2 per row; transform
    // (v - 0.5f) * pi/2 exactly as the reference; duplicate into f32x2 lanes.
    unsigned long long P[18];
    const bool tail_ok = (j0 <= W_IN - 6);   // false only for j0 == 380
    #pragma unroll
    for (int r = 0; r < 3; ++r) {
        const float* rp = xb + (i + r) * W_IN + j0;
        float4 v4 = *reinterpret_cast<const float4*>(rp);
        float2 v2 = tail_ok ? *reinterpret_cast<const float2*>(rp + 4)
                            : make_float2(0.f, 0.f);
        float v[6] = { v4.x, v4.y, v4.z, v4.w, v2.x, v2.y };
        #pragma unroll
        for (int c = 0; c < 6; ++c)
            P[r * 6 + c] = dup2((v[c] - 0.5f) * c0);
    }

    float best[4];
    int   bi[4];
    #pragma unroll
    for (int p = 0; p < 4; ++p) { best[p] = -3.4e38f; bi[p] = 0; }

    // P-offset of weight k within the row-stride-6 window.
    const int off[9] = { 0, 1, 2, 6, 7, 8, 12, 13, 14 };

    #pragma unroll 8
    for (int q = 0; q < 16; ++q) {
        // Warp-uniform LDC.128s: 4 bias values + 4 states' weights per k.
        const ulonglong2 bq = cquad(cB + 4 * q);   // .x=(b[4q],b[4q+1]) .y=(b[4q+2],b[4q+3])
        ulonglong2 wq[9];
        #pragma unroll
        for (int k = 0; k < NB; ++k)
            wq[k] = cquad(cW + k * KST + 4 * q);

        // Two packed accumulator sets: L = states (4q,4q+1), H = (4q+2,4q+3).
        // Bit-identical per-state order: (((p0*w0 + p1*w1) + ... ) + b)
        unsigned long long aL[4], aH[4];
        #pragma unroll
        for (int p = 0; p < 4; ++p) {
            aL[p] = mul2(P[p], wq[0].x);
            aH[p] = mul2(P[p], wq[0].y);
        }
        #pragma unroll
        for (int k = 1; k < NB; ++k) {
            #pragma unroll
            for (int p = 0; p < 4; ++p) {
                aL[p] = fma2(P[off[k] + p], wq[k].x, aL[p]);
                aH[p] = fma2(P[off[k] + p], wq[k].y, aH[p]);
            }
        }
        #pragma unroll
        for (int p = 0; p < 4; ++p) {
            aL[p] = add2(aL[p], bq.x);
            aH[p] = add2(aH[p], bq.y);
        }

        // Argmax tournament, ascending-index-first semantics preserved:
        // pair winners via strict > (hi wins only if strictly greater),
        // quad winner via strict > (H-pair wins only if strictly greater),
        // best update via strict > (first occurrence kept).
        const int s0 = q * 4;
        #pragma unroll
        for (int p = 0; p < 4; ++p) {
            float lo1, hi1, lo2, hi2;
            unpack2(aL[p], lo1, hi1);
            unpack2(aH[p], lo2, hi2);
            const bool  q1 = hi1 > lo1;
            const float c1 = q1 ? hi1 : lo1;
            const int   i1 = q1 ? s0 + 1 : s0;
            const bool  q2 = hi2 > lo2;
            const float c2 = q2 ? hi2 : lo2;
            const int   i2 = q2 ? s0 + 3 : s0 + 2;
            const bool  qq = c2 > c1;
            const float cq = qq ? c2 : c1;
            const int   iq = qq ? i2 : i1;
            if (cq > best[p]) { best[p] = cq; bi[p] = iq; }
        }
    }

    // Decode + store: gather winning key rows directly from global (int ->
    // float conversion exact for 0..3), float2 stores (8B-aligned: j0 even;
    // odd output rows are 8-mod-16 aligned so STG.128 is not legal here).
    const int obase = bz * (NB * HOWO) + i * WO + j0;
    const int* k0 = keys + bi[0] * NB;
    const int* k1 = keys + bi[1] * NB;
    const int* k2 = keys + bi[2] * NB;
    const int* k3 = keys + bi[3] * NB;
    const bool hi_ok = (j0 + 3 < WO);
    #pragma unroll
    for (int k = 0; k < NB; ++k) {
        float* op = out + obase + k * HOWO;
        *reinterpret_cast<float2*>(op) =
            make_float2((float)__ldg(k0 + k), (float)__ldg(k1 + k));
        if (hi_ok)
            *reinterpret_cast<float2*>(op + 2) =
                make_float2((float)__ldg(k2 + k), (float)__ldg(k3 + k));
    }
}

extern "C" void kernel_launch(void* const* d_in, const int* in_sizes, int n_in,
                              void* d_out, int out_size) {
    const float* x    = (const float*)d_in[0];
    const float* W    = (const float*)d_in[1];
    const float* b    = (const float*)d_in[2];
    const int*   keys = (const int*)d_in[3];
    float*       out  = (float*)d_out;

    // Device-to-device async copies into constant memory (graph-capturable).
    cudaMemcpyToSymbolAsync(cW, W, NB * KST * sizeof(float), 0,
                            cudaMemcpyDeviceToDevice);
    cudaMemcpyToSymbolAsync(cB, b, KST * sizeof(float), 0,
                            cudaMemcpyDeviceToDevice);

    dim3 block(32, 2);                 // 64 threads
    dim3 grid(3, HO / 2, B_N);         // (3, 191, 8) = 4584 blocks
    qconv_kernel<<<grid, block>>>(x, keys, out);
}